// round 2
// baseline (speedup 1.0000x reference)
#include <cuda_runtime.h>
#include <math.h>

#define DM 2048   // d_model
#define DF 8192   // d_ff
#define NT 8192   // tokens

// Scratch: H intermediate (reused per expert) + per-token gate weights.
__device__ float g_H[(size_t)NT * DF];      // 256 MB
__device__ float g_gate[2 * NT];

__global__ void gate_k(const int* __restrict__ ids, const float* __restrict__ w,
                       float* __restrict__ gate) {
    int i = blockIdx.x * blockDim.x + threadIdx.x;
    if (i >= NT) return;
    int a = ids[2 * i] & 1;
    int b = ids[2 * i + 1] & 1;
    float wa = w[2 * i], wb = w[2 * i + 1];
    gate[i]      = (a ? 0.f : wa) + (b ? 0.f : wb);   // weight for expert 0
    gate[NT + i] = (a ? wa : 0.f) + (b ? wb : 0.f);   // weight for expert 1
}

// MODE 0: C = GELU(A@B + bias)              (writes H)
// MODE 1: C = gate[row] * (A@B + bias)      (first expert -> overwrite out)
// MODE 2: C += gate[row] * (A@B + bias)     (second expert -> accumulate)
template <int MODE>
__global__ __launch_bounds__(256)
void sgemm128(const float* __restrict__ A, const float* __restrict__ B,
              const float* __restrict__ bias, const float* __restrict__ gate,
              float* __restrict__ C, int M, int N, int K) {
    __shared__ float As[8][128];   // transposed A tile: As[k][m]
    __shared__ float Bs[8][128];   // Bs[k][n]

    const int t  = threadIdx.x;
    const int tx = t & 15;         // 16 cols of threads
    const int ty = t >> 4;         // 16 rows of threads
    const int bm = blockIdx.y * 128;
    const int bn = blockIdx.x * 128;

    float acc[8][8] = {};

    const int arow = t >> 1, acol = (t & 1) * 4;   // A tile: 128 rows x 8 cols
    const int brow = t >> 5, bcol = (t & 31) * 4;  // B tile: 8 rows x 128 cols

    const float* Ag = A + (size_t)(bm + arow) * K + acol;
    const float* Bg = B + (size_t)brow * N + bn + bcol;

    for (int kt = 0; kt < K; kt += 8) {
        float4 av = *(const float4*)(Ag + kt);
        float4 bv = *(const float4*)(Bg + (size_t)kt * N);
        __syncthreads();
        As[acol + 0][arow] = av.x;
        As[acol + 1][arow] = av.y;
        As[acol + 2][arow] = av.z;
        As[acol + 3][arow] = av.w;
        *(float4*)&Bs[brow][bcol] = bv;
        __syncthreads();
#pragma unroll
        for (int k = 0; k < 8; k++) {
            float ar[8], br[8];
            *(float4*)(ar)     = *(const float4*)&As[k][ty * 8];
            *(float4*)(ar + 4) = *(const float4*)&As[k][ty * 8 + 4];
            *(float4*)(br)     = *(const float4*)&Bs[k][tx * 8];
            *(float4*)(br + 4) = *(const float4*)&Bs[k][tx * 8 + 4];
#pragma unroll
            for (int i = 0; i < 8; i++)
#pragma unroll
                for (int j = 0; j < 8; j++)
                    acc[i][j] = fmaf(ar[i], br[j], acc[i][j]);
        }
    }

    // Epilogue
    float bc[8];
    *(float4*)(bc)     = *(const float4*)(bias + bn + tx * 8);
    *(float4*)(bc + 4) = *(const float4*)(bias + bn + tx * 8 + 4);

#pragma unroll
    for (int i = 0; i < 8; i++) {
        int row = bm + ty * 8 + i;
        float g = (MODE == 0) ? 0.f : gate[row];
        float ov[8];
#pragma unroll
        for (int j = 0; j < 8; j++) {
            float v = acc[i][j] + bc[j];
            if (MODE == 0) {
                // exact GELU: 0.5*x*(1+erf(x/sqrt(2)))
                v = 0.5f * v * (1.0f + erff(v * 0.70710678118654752f));
            } else {
                v *= g;
            }
            ov[j] = v;
        }
        float* Cp = C + (size_t)row * N + bn + tx * 8;
        if (MODE == 2) {
            float4 o0 = *(float4*)(ov), o1 = *(float4*)(ov + 4);
            float4 c0 = *(const float4*)(Cp), c1 = *(const float4*)(Cp + 4);
            o0.x += c0.x; o0.y += c0.y; o0.z += c0.z; o0.w += c0.w;
            o1.x += c1.x; o1.y += c1.y; o1.z += c1.z; o1.w += c1.w;
            *(float4*)(Cp)     = o0;
            *(float4*)(Cp + 4) = o1;
        } else {
            *(float4*)(Cp)     = *(float4*)(ov);
            *(float4*)(Cp + 4) = *(float4*)(ov + 4);
        }
    }
}

extern "C" void kernel_launch(void* const* d_in, const int* in_sizes, int n_in,
                              void* d_out, int out_size) {
    const float* x   = (const float*)d_in[0];
    const int*   ids = (const int*)  d_in[1];
    const float* tw  = (const float*)d_in[2];
    const float* W1[2] = {(const float*)d_in[3], (const float*)d_in[7]};
    const float* b1[2] = {(const float*)d_in[4], (const float*)d_in[8]};
    const float* W2[2] = {(const float*)d_in[5], (const float*)d_in[9]};
    const float* b2[2] = {(const float*)d_in[6], (const float*)d_in[10]};
    float* out = (float*)d_out;

    float* H = nullptr;
    float* gate = nullptr;
    cudaGetSymbolAddress((void**)&H, g_H);
    cudaGetSymbolAddress((void**)&gate, g_gate);

    gate_k<<<(NT + 255) / 256, 256>>>(ids, tw, gate);

    dim3 blk(256);
    dim3 grid1(DF / 128, NT / 128);   // GEMM1: M=NT, N=DF, K=DM
    dim3 grid2(DM / 128, NT / 128);   // GEMM2: M=NT, N=DM, K=DF

    // expert 0
    sgemm128<0><<<grid1, blk>>>(x, W1[0], b1[0], nullptr, H,   NT, DF, DM);
    sgemm128<1><<<grid2, blk>>>(H, W2[0], b2[0], gate,    out, NT, DM, DF);
    // expert 1
    sgemm128<0><<<grid1, blk>>>(x, W1[1], b1[1], nullptr,   H,   NT, DF, DM);
    sgemm128<2><<<grid2, blk>>>(H, W2[1], b2[1], gate + NT, out, NT, DM, DF);
}

// round 4
// speedup vs baseline: 3.0926x; 3.0926x over previous
#include <cuda_runtime.h>
#include <cuda_bf16.h>
#include <cstdint>
#include <math.h>

#define DM 2048
#define DF 8192
#define NT 8192

// ---------------- scratch (device globals; no allocs allowed) ----------------
__device__ __align__(256) __nv_bfloat16 g_Xh[(size_t)NT * DM];
__device__ __align__(256) __nv_bfloat16 g_Xl[(size_t)NT * DM];
__device__ __align__(256) __nv_bfloat16 g_Hh[(size_t)NT * DF];
__device__ __align__(256) __nv_bfloat16 g_Hl[(size_t)NT * DF];
__device__ __align__(256) __nv_bfloat16 g_W1t[2][2][(size_t)DF * DM]; // [expert][hi/lo][N][K]
__device__ __align__(256) __nv_bfloat16 g_W2t[2][2][(size_t)DM * DF]; // [expert][hi/lo][N][K]
__device__ float g_gate[2 * NT];

// ---------------- helpers ----------------
__device__ __forceinline__ uint32_t smem_u32(const void* p) {
    uint32_t a;
    asm("{ .reg .u64 t; cvta.to.shared.u64 t, %1; cvt.u32.u64 %0, t; }" : "=r"(a) : "l"(p));
    return a;
}
#define CP_ASYNC16(sa, g) \
    asm volatile("cp.async.cg.shared.global [%0], [%1], 16;" :: "r"(sa), "l"(g))
#define CP_COMMIT() asm volatile("cp.async.commit_group;" ::: "memory")
#define CP_WAIT(n)  asm volatile("cp.async.wait_group %0;" :: "n"(n) : "memory")

#define LDSM_X4(r0, r1, r2, r3, a) \
    asm volatile("ldmatrix.sync.aligned.m8n8.x4.shared.b16 {%0,%1,%2,%3}, [%4];" \
                 : "=r"(r0), "=r"(r1), "=r"(r2), "=r"(r3) : "r"(a))

__device__ __forceinline__ void mma16816(float* d, const uint32_t* a, const uint32_t* b) {
    asm volatile(
        "mma.sync.aligned.m16n8k16.row.col.f32.bf16.bf16.f32 "
        "{%0,%1,%2,%3}, {%4,%5,%6,%7}, {%8,%9}, {%0,%1,%2,%3};"
        : "+f"(d[0]), "+f"(d[1]), "+f"(d[2]), "+f"(d[3])
        : "r"(a[0]), "r"(a[1]), "r"(a[2]), "r"(a[3]), "r"(b[0]), "r"(b[1]));
}

// swizzled byte offset within one 128x32-bf16 (8KB) tile; r=row(0..127), s=16B-seg(0..3)
__device__ __forceinline__ uint32_t swz(uint32_t r, uint32_t s) {
    return ((r >> 1) << 7) + (((((r & 1) << 2) | s) ^ ((r >> 1) & 7)) << 4);
}

// ---------------- small prep kernels ----------------
__global__ void gate_k(const int* __restrict__ ids, const float* __restrict__ w,
                       float* __restrict__ gate) {
    int i = blockIdx.x * blockDim.x + threadIdx.x;
    if (i >= NT) return;
    int a = ids[2 * i] & 1, b = ids[2 * i + 1] & 1;
    float wa = w[2 * i], wb = w[2 * i + 1];
    gate[i]      = (a ? 0.f : wa) + (b ? 0.f : wb);
    gate[NT + i] = (a ? wa : 0.f) + (b ? wb : 0.f);
}

__global__ void split_k(const float* __restrict__ x, __nv_bfloat16* __restrict__ hi,
                        __nv_bfloat16* __restrict__ lo, size_t n) {
    size_t i = (size_t)blockIdx.x * blockDim.x + threadIdx.x;
    if (i >= n) return;
    float v = x[i];
    __nv_bfloat16 h = __float2bfloat16(v);
    hi[i] = h;
    lo[i] = __float2bfloat16(v - __bfloat162float(h));
}

// W [K][N] f32 -> Wt hi/lo [N][K] bf16
__global__ void transpose_split(const float* __restrict__ W,
                                __nv_bfloat16* __restrict__ th,
                                __nv_bfloat16* __restrict__ tl, int K, int N) {
    __shared__ float tile[32][33];
    int k0 = blockIdx.y * 32, n0 = blockIdx.x * 32;
    int tx = threadIdx.x;
    for (int r = threadIdx.y; r < 32; r += 8)
        tile[r][tx] = W[(size_t)(k0 + r) * N + n0 + tx];
    __syncthreads();
    for (int r = threadIdx.y; r < 32; r += 8) {
        float v = tile[tx][r];
        __nv_bfloat16 h = __float2bfloat16(v);
        size_t o = (size_t)(n0 + r) * K + k0 + tx;
        th[o] = h;
        tl[o] = __float2bfloat16(v - __bfloat162float(h));
    }
}

// ---------------- mma.sync split-bf16 GEMM ----------------
// C[M,Ntot] = A @ B^T (+bias, epilogue). A:[M][K] hi/lo bf16, B:[Ntot][K] hi/lo bf16.
static constexpr int BM = 128, BN = 128, BK = 32;
static constexpr int STAGES = 4;
static constexpr int TILE_B = 8192;           // bytes per 128x32 bf16 tile
static constexpr int STAGE_B = 4 * TILE_B;    // Ah, Al, Bh, Bl
static constexpr int SMEM_BYTES = STAGES * STAGE_B;  // 131072
static constexpr int O_AH = 0, O_AL = TILE_B, O_BH = 2 * TILE_B, O_BL = 3 * TILE_B;

// Load one 128x32 tile (hi and lo) from K-major global into swizzled smem.
__device__ __forceinline__ void load_pair(uint32_t sdst_h, uint32_t sdst_l,
                                          const __nv_bfloat16* __restrict__ gh,
                                          const __nv_bfloat16* __restrict__ gl,
                                          int ld, int t) {
#pragma unroll
    for (int i = 0; i < 2; i++) {
        uint32_t idx = t + i * 256;
        uint32_t r = idx >> 2, s = idx & 3;
        uint32_t off = swz(r, s);
        size_t go = (size_t)r * ld + s * 8;
        CP_ASYNC16(sdst_h + off, gh + go);
        CP_ASYNC16(sdst_l + off, gl + go);
    }
}

// EPI 0: Hh/Hl = split(GELU(v+bias))   EPI 1: Cf = gate*(v+bias)   EPI 2: Cf += gate*(v+bias)
template <int EPI>
__global__ void __launch_bounds__(256, 1)
moe_gemm(const __nv_bfloat16* __restrict__ Ah, const __nv_bfloat16* __restrict__ Al,
         const __nv_bfloat16* __restrict__ Bh, const __nv_bfloat16* __restrict__ Bl,
         const float* __restrict__ bias, const float* __restrict__ gate,
         float* __restrict__ Cf, __nv_bfloat16* __restrict__ Ch,
         __nv_bfloat16* __restrict__ Cl, int K, int Ntot) {
    extern __shared__ char smem[];
    const uint32_t sb = smem_u32(smem);
    const int t = threadIdx.x, wid = t >> 5, lid = t & 31;
    const int wm = wid >> 2, wn = wid & 3;       // warp grid 2x4 -> tile 64x32
    const int bm = blockIdx.y * BM, bn = blockIdx.x * BN;

    const __nv_bfloat16* a_h = Ah + (size_t)bm * K;
    const __nv_bfloat16* a_l = Al + (size_t)bm * K;
    const __nv_bfloat16* b_h = Bh + (size_t)bn * K;
    const __nv_bfloat16* b_l = Bl + (size_t)bn * K;
    const int NC = K / BK;

    float acc[4][4][4];
#pragma unroll
    for (int i = 0; i < 4; i++)
#pragma unroll
        for (int j = 0; j < 4; j++)
#pragma unroll
            for (int q = 0; q < 4; q++) acc[i][j][q] = 0.f;

    // prologue: stages 0..STAGES-2
#pragma unroll
    for (int p = 0; p < STAGES - 1; p++) {
        uint32_t st = sb + p * STAGE_B;
        int kt = p * BK;
        load_pair(st + O_AH, st + O_AL, a_h + kt, a_l + kt, K, t);
        load_pair(st + O_BH, st + O_BL, b_h + kt, b_l + kt, K, t);
        CP_COMMIT();
    }

    // precompute lane-invariant ldmatrix row/seg pieces
    const uint32_t a_r = (uint32_t)(lid & 15);           // + wm*64 + mt*16
    const uint32_t a_s = (uint32_t)(lid >> 4);           // + kk*2
    const uint32_t b_r = (uint32_t)((lid & 7) + ((lid >> 4) << 3));  // + wn*32 + nt2*16
    const uint32_t b_s = (uint32_t)((lid >> 3) & 1);     // + kk*2

    for (int c = 0; c < NC; c++) {
        CP_WAIT(STAGES - 2);
        __syncthreads();
        // issue loads for stage c+STAGES-1 (overwrites stage computed last iter)
        if (c + STAGES - 1 < NC) {
            uint32_t st = sb + ((c + STAGES - 1) % STAGES) * STAGE_B;
            int kt = (c + STAGES - 1) * BK;
            load_pair(st + O_AH, st + O_AL, a_h + kt, a_l + kt, K, t);
            load_pair(st + O_BH, st + O_BL, b_h + kt, b_l + kt, K, t);
        }
        CP_COMMIT();

        const uint32_t st = sb + (c % STAGES) * STAGE_B;
#pragma unroll
        for (int kk = 0; kk < 2; kk++) {
            uint32_t ah[4][4], al[4][4], bh[2][4], bl[2][4];
#pragma unroll
            for (int mt = 0; mt < 4; mt++) {
                uint32_t off = swz(wm * 64 + mt * 16 + a_r, kk * 2 + a_s);
                LDSM_X4(ah[mt][0], ah[mt][1], ah[mt][2], ah[mt][3], st + O_AH + off);
                LDSM_X4(al[mt][0], al[mt][1], al[mt][2], al[mt][3], st + O_AL + off);
            }
#pragma unroll
            for (int p = 0; p < 2; p++) {  // n16 pair -> two n8 tiles
                uint32_t off = swz(wn * 32 + p * 16 + b_r, kk * 2 + b_s);
                LDSM_X4(bh[p][0], bh[p][1], bh[p][2], bh[p][3], st + O_BH + off);
                LDSM_X4(bl[p][0], bl[p][1], bl[p][2], bl[p][3], st + O_BL + off);
            }
#pragma unroll
            for (int mt = 0; mt < 4; mt++)
#pragma unroll
                for (int nt = 0; nt < 4; nt++) {
                    const uint32_t* Bhf = &bh[nt >> 1][(nt & 1) << 1];
                    const uint32_t* Blf = &bl[nt >> 1][(nt & 1) << 1];
                    mma16816(acc[mt][nt], ah[mt], Bhf);
                    mma16816(acc[mt][nt], ah[mt], Blf);
                    mma16816(acc[mt][nt], al[mt], Bhf);
                }
        }
    }

    // ---------------- epilogue ----------------
    const int lr = lid >> 2, lc = (lid & 3) << 1;
#pragma unroll
    for (int mt = 0; mt < 4; mt++) {
        int row0 = bm + wm * 64 + mt * 16 + lr;
        float g0 = (EPI == 0) ? 0.f : gate[row0];
        float g1 = (EPI == 0) ? 0.f : gate[row0 + 8];
#pragma unroll
        for (int nt = 0; nt < 4; nt++) {
            int col = bn + wn * 32 + nt * 8 + lc;
            float bv0 = bias[col], bv1 = bias[col + 1];
#pragma unroll
            for (int h = 0; h < 2; h++) {  // h=0: rows lr, h=1: rows lr+8
                int row = row0 + h * 8;
                float v0 = acc[mt][nt][2 * h + 0] + bv0;
                float v1 = acc[mt][nt][2 * h + 1] + bv1;
                size_t o = (size_t)row * Ntot + col;
                if (EPI == 0) {
                    v0 = 0.5f * v0 * (1.0f + erff(v0 * 0.70710678118654752f));
                    v1 = 0.5f * v1 * (1.0f + erff(v1 * 0.70710678118654752f));
                    __nv_bfloat16 h0 = __float2bfloat16(v0);
                    __nv_bfloat16 h1 = __float2bfloat16(v1);
                    __nv_bfloat162 hh; hh.x = h0; hh.y = h1;
                    __nv_bfloat162 ll;
                    ll.x = __float2bfloat16(v0 - __bfloat162float(h0));
                    ll.y = __float2bfloat16(v1 - __bfloat162float(h1));
                    *reinterpret_cast<__nv_bfloat162*>(Ch + o) = hh;
                    *reinterpret_cast<__nv_bfloat162*>(Cl + o) = ll;
                } else {
                    float g = h ? g1 : g0;
                    float2* p = reinterpret_cast<float2*>(Cf + o);
                    if (EPI == 1) {
                        float2 w; w.x = g * v0; w.y = g * v1;
                        *p = w;
                    } else {
                        float2 w = *p;
                        w.x += g * v0; w.y += g * v1;
                        *p = w;
                    }
                }
            }
        }
    }
}

// ---------------- launch ----------------
extern "C" void kernel_launch(void* const* d_in, const int* in_sizes, int n_in,
                              void* d_out, int out_size) {
    const float* x   = (const float*)d_in[0];
    const int*   ids = (const int*)d_in[1];
    const float* tw  = (const float*)d_in[2];
    const float* W1[2] = {(const float*)d_in[3], (const float*)d_in[7]};
    const float* b1[2] = {(const float*)d_in[4], (const float*)d_in[8]};
    const float* W2[2] = {(const float*)d_in[5], (const float*)d_in[9]};
    const float* b2[2] = {(const float*)d_in[6], (const float*)d_in[10]};
    float* out = (float*)d_out;

    __nv_bfloat16 *Xh, *Xl, *Hh, *Hl, *W1t, *W2t;
    float* gate;
    cudaGetSymbolAddress((void**)&Xh, g_Xh);
    cudaGetSymbolAddress((void**)&Xl, g_Xl);
    cudaGetSymbolAddress((void**)&Hh, g_Hh);
    cudaGetSymbolAddress((void**)&Hl, g_Hl);
    cudaGetSymbolAddress((void**)&W1t, g_W1t);
    cudaGetSymbolAddress((void**)&W2t, g_W2t);
    cudaGetSymbolAddress((void**)&gate, g_gate);

    cudaFuncSetAttribute(moe_gemm<0>, cudaFuncAttributeMaxDynamicSharedMemorySize, SMEM_BYTES);
    cudaFuncSetAttribute(moe_gemm<1>, cudaFuncAttributeMaxDynamicSharedMemorySize, SMEM_BYTES);
    cudaFuncSetAttribute(moe_gemm<2>, cudaFuncAttributeMaxDynamicSharedMemorySize, SMEM_BYTES);

    gate_k<<<(NT + 255) / 256, 256>>>(ids, tw, gate);
    {
        size_t n = (size_t)NT * DM;
        split_k<<<(unsigned)((n + 255) / 256), 256>>>(x, Xh, Xl, n);
    }
    for (int e = 0; e < 2; e++) {
        transpose_split<<<dim3(DF / 32, DM / 32), dim3(32, 8)>>>(
            W1[e], W1t + ((size_t)e * 2 + 0) * DF * DM, W1t + ((size_t)e * 2 + 1) * DF * DM,
            DM, DF);
        transpose_split<<<dim3(DM / 32, DF / 32), dim3(32, 8)>>>(
            W2[e], W2t + ((size_t)e * 2 + 0) * DM * DF, W2t + ((size_t)e * 2 + 1) * DM * DF,
            DF, DM);
    }

    dim3 blk(256);
    dim3 g1(DF / BN, NT / BM);   // (64, 64)
    dim3 g2(DM / BN, NT / BM);   // (16, 64)

    for (int e = 0; e < 2; e++) {
        moe_gemm<0><<<g1, blk, SMEM_BYTES>>>(
            Xh, Xl, W1t + ((size_t)e * 2 + 0) * DF * DM, W1t + ((size_t)e * 2 + 1) * DF * DM,
            b1[e], nullptr, nullptr, Hh, Hl, DM, DF);
        if (e == 0)
            moe_gemm<1><<<g2, blk, SMEM_BYTES>>>(
                Hh, Hl, W2t + 0 * (size_t)DM * DF, W2t + 1 * (size_t)DM * DF,
                b2[0], gate, out, nullptr, nullptr, DF, DM);
        else
            moe_gemm<2><<<g2, blk, SMEM_BYTES>>>(
                Hh, Hl, W2t + 2 * (size_t)DM * DF, W2t + 3 * (size_t)DM * DF,
                b2[1], gate + NT, out, nullptr, nullptr, DF, DM);
    }
}

// round 5
// speedup vs baseline: 3.1497x; 1.0184x over previous
#include <cuda_runtime.h>
#include <cuda_bf16.h>
#include <cstdint>
#include <math.h>

#define DM 2048
#define DF 8192
#define NT 8192

// ---------------- scratch (device globals; no allocs allowed) ----------------
__device__ __align__(256) __nv_bfloat16 g_Xh[(size_t)NT * DM];
__device__ __align__(256) __nv_bfloat16 g_Xl[(size_t)NT * DM];
// H concat: [M][2*DF], expert e at column offset e*DF. Pre-scaled by gate.
__device__ __align__(256) __nv_bfloat16 g_Hh[(size_t)NT * 2 * DF];
__device__ __align__(256) __nv_bfloat16 g_Hl[(size_t)NT * 2 * DF];
__device__ __align__(256) __nv_bfloat16 g_W1t[2][2][(size_t)DF * DM]; // [expert][hi/lo][N][K]
__device__ __align__(256) __nv_bfloat16 g_W2t[2][2][(size_t)DM * DF]; // [expert][hi/lo][N][K]
__device__ float g_gate[2 * NT];

// ---------------- helpers ----------------
__device__ __forceinline__ uint32_t smem_u32(const void* p) {
    uint32_t a;
    asm("{ .reg .u64 t; cvta.to.shared.u64 t, %1; cvt.u32.u64 %0, t; }" : "=r"(a) : "l"(p));
    return a;
}
#define CP_ASYNC16(sa, g) \
    asm volatile("cp.async.cg.shared.global [%0], [%1], 16;" :: "r"(sa), "l"(g))
#define CP_COMMIT() asm volatile("cp.async.commit_group;" ::: "memory")
#define CP_WAIT(n)  asm volatile("cp.async.wait_group %0;" :: "n"(n) : "memory")

#define LDSM_X4(r0, r1, r2, r3, a) \
    asm volatile("ldmatrix.sync.aligned.m8n8.x4.shared.b16 {%0,%1,%2,%3}, [%4];" \
                 : "=r"(r0), "=r"(r1), "=r"(r2), "=r"(r3) : "r"(a))

__device__ __forceinline__ void mma16816(float* d, const uint32_t* a, const uint32_t* b) {
    asm volatile(
        "mma.sync.aligned.m16n8k16.row.col.f32.bf16.bf16.f32 "
        "{%0,%1,%2,%3}, {%4,%5,%6,%7}, {%8,%9}, {%0,%1,%2,%3};"
        : "+f"(d[0]), "+f"(d[1]), "+f"(d[2]), "+f"(d[3])
        : "r"(a[0]), "r"(a[1]), "r"(a[2]), "r"(a[3]), "r"(b[0]), "r"(b[1]));
}

// swizzled byte offset in a tile of 64B rows; r=row, s=16B segment (0..3)
__device__ __forceinline__ uint32_t swz(uint32_t r, uint32_t s) {
    return ((r >> 1) << 7) + (((((r & 1) << 2) | s) ^ ((r >> 1) & 7)) << 4);
}

// ---------------- small prep kernels ----------------
__global__ void gate_k(const int* __restrict__ ids, const float* __restrict__ w,
                       float* __restrict__ gate) {
    int i = blockIdx.x * blockDim.x + threadIdx.x;
    if (i >= NT) return;
    int a = ids[2 * i] & 1, b = ids[2 * i + 1] & 1;
    float wa = w[2 * i], wb = w[2 * i + 1];
    gate[i]      = (a ? 0.f : wa) + (b ? 0.f : wb);
    gate[NT + i] = (a ? wa : 0.f) + (b ? wb : 0.f);
}

__global__ void split_k(const float* __restrict__ x, __nv_bfloat16* __restrict__ hi,
                        __nv_bfloat16* __restrict__ lo, size_t n) {
    size_t i = (size_t)blockIdx.x * blockDim.x + threadIdx.x;
    if (i >= n) return;
    float v = x[i];
    __nv_bfloat16 h = __float2bfloat16(v);
    hi[i] = h;
    lo[i] = __float2bfloat16(v - __bfloat162float(h));
}

// W [K][N] f32 -> Wt hi/lo [N][K] bf16
__global__ void transpose_split(const float* __restrict__ W,
                                __nv_bfloat16* __restrict__ th,
                                __nv_bfloat16* __restrict__ tl, int K, int N) {
    __shared__ float tile[32][33];
    int k0 = blockIdx.y * 32, n0 = blockIdx.x * 32;
    int tx = threadIdx.x;
    for (int r = threadIdx.y; r < 32; r += 8)
        tile[r][tx] = W[(size_t)(k0 + r) * N + n0 + tx];
    __syncthreads();
    for (int r = threadIdx.y; r < 32; r += 8) {
        float v = tile[tx][r];
        __nv_bfloat16 h = __float2bfloat16(v);
        size_t o = (size_t)(n0 + r) * K + k0 + tx;
        th[o] = h;
        tl[o] = __float2bfloat16(v - __bfloat162float(h));
    }
}

// ---------------- mma.sync split-bf16 GEMM, CTA tile 128x256 ----------------
static constexpr int BM = 128, BN = 256, BK = 32;
static constexpr int STAGES = 4;
static constexpr int A_TILE_B = BM * 64;      // 8192 B (BM rows x 64B)
static constexpr int B_TILE_B = BN * 64;      // 16384 B
static constexpr int STAGE_B = 2 * A_TILE_B + 2 * B_TILE_B;  // 49152
static constexpr int SMEM_BYTES = STAGES * STAGE_B;           // 196608
static constexpr int O_AH = 0, O_AL = A_TILE_B;
static constexpr int O_BH = 2 * A_TILE_B, O_BL = 2 * A_TILE_B + B_TILE_B;

template <int ITERS>
__device__ __forceinline__ void load_pair(uint32_t sdst_h, uint32_t sdst_l,
                                          const __nv_bfloat16* __restrict__ gh,
                                          const __nv_bfloat16* __restrict__ gl,
                                          int ld, int t) {
#pragma unroll
    for (int i = 0; i < ITERS; i++) {
        uint32_t idx = t + i * 256;
        uint32_t r = idx >> 2, s = idx & 3;
        uint32_t off = swz(r, s);
        size_t go = (size_t)r * ld + s * 8;
        CP_ASYNC16(sdst_h + off, gh + go);
        CP_ASYNC16(sdst_l + off, gl + go);
    }
}

// EPI 0: Ch/Cl = split(gate[row] * GELU(v + bias0[col]))          (GEMM1)
// EPI 1: Cf    = v + gate0[row]*bias0[col] + gate1[row]*bias1[col] (GEMM2 combined)
template <int EPI>
__global__ void __launch_bounds__(256, 1)
moe_gemm(const __nv_bfloat16* __restrict__ Ah, const __nv_bfloat16* __restrict__ Al,
         const __nv_bfloat16* __restrict__ Bh0, const __nv_bfloat16* __restrict__ Bl0,
         const __nv_bfloat16* __restrict__ Bh1, const __nv_bfloat16* __restrict__ Bl1,
         const float* __restrict__ bias0, const float* __restrict__ bias1,
         const float* __restrict__ gate,
         float* __restrict__ Cf, __nv_bfloat16* __restrict__ Ch,
         __nv_bfloat16* __restrict__ Cl,
         int K, int lda, int ldb, int ldc, int k_split, int coff) {
    extern __shared__ char smem[];
    const uint32_t sb = smem_u32(smem);
    const int t = threadIdx.x, wid = t >> 5, lid = t & 31;
    const int wm = wid >> 2, wn = wid & 3;   // 2x4 warp grid; warp tile 64x64
    const int bm = blockIdx.y * BM, bn = blockIdx.x * BN;
    const int NC = K / BK;

    const __nv_bfloat16* a_h = Ah + (size_t)bm * lda;
    const __nv_bfloat16* a_l = Al + (size_t)bm * lda;

    float acc[4][8][4];
#pragma unroll
    for (int i = 0; i < 4; i++)
#pragma unroll
        for (int j = 0; j < 8; j++)
#pragma unroll
            for (int q = 0; q < 4; q++) acc[i][j][q] = 0.f;

    // prologue: stages 0..STAGES-2
#pragma unroll
    for (int p = 0; p < STAGES - 1; p++) {
        uint32_t st = sb + p * STAGE_B;
        int e = (p >= k_split);
        int kb = (p - (e ? k_split : 0)) * BK;
        const __nv_bfloat16* bh = (e ? Bh1 : Bh0) + (size_t)bn * ldb + kb;
        const __nv_bfloat16* bl = (e ? Bl1 : Bl0) + (size_t)bn * ldb + kb;
        load_pair<2>(st + O_AH, st + O_AL, a_h + p * BK, a_l + p * BK, lda, t);
        load_pair<4>(st + O_BH, st + O_BL, bh, bl, ldb, t);
        CP_COMMIT();
    }

    const uint32_t a_r = (uint32_t)(lid & 15);
    const uint32_t a_s = (uint32_t)(lid >> 4);
    const uint32_t b_r = (uint32_t)((lid & 7) + ((lid >> 4) << 3));
    const uint32_t b_s = (uint32_t)((lid >> 3) & 1);

    for (int c = 0; c < NC; c++) {
        CP_WAIT(STAGES - 2);
        __syncthreads();
        if (c + STAGES - 1 < NC) {
            int cc = c + STAGES - 1;
            uint32_t st = sb + (cc % STAGES) * STAGE_B;
            int e = (cc >= k_split);
            int kb = (cc - (e ? k_split : 0)) * BK;
            const __nv_bfloat16* bh = (e ? Bh1 : Bh0) + (size_t)bn * ldb + kb;
            const __nv_bfloat16* bl = (e ? Bl1 : Bl0) + (size_t)bn * ldb + kb;
            load_pair<2>(st + O_AH, st + O_AL, a_h + cc * BK, a_l + cc * BK, lda, t);
            load_pair<4>(st + O_BH, st + O_BL, bh, bl, ldb, t);
        }
        CP_COMMIT();

        const uint32_t st = sb + (c % STAGES) * STAGE_B;
#pragma unroll
        for (int kk = 0; kk < 2; kk++) {
            uint32_t ah[4][4], al[4][4], bh[4][4], bl[4][4];
#pragma unroll
            for (int mt = 0; mt < 4; mt++) {
                uint32_t off = swz(wm * 64 + mt * 16 + a_r, kk * 2 + a_s);
                LDSM_X4(ah[mt][0], ah[mt][1], ah[mt][2], ah[mt][3], st + O_AH + off);
                LDSM_X4(al[mt][0], al[mt][1], al[mt][2], al[mt][3], st + O_AL + off);
            }
#pragma unroll
            for (int p = 0; p < 4; p++) {   // 4 n16 groups cover 64 cols
                uint32_t off = swz(wn * 64 + p * 16 + b_r, kk * 2 + b_s);
                LDSM_X4(bh[p][0], bh[p][1], bh[p][2], bh[p][3], st + O_BH + off);
                LDSM_X4(bl[p][0], bl[p][1], bl[p][2], bl[p][3], st + O_BL + off);
            }
#pragma unroll
            for (int mt = 0; mt < 4; mt++)
#pragma unroll
                for (int nt = 0; nt < 8; nt++) {
                    const uint32_t* Bhf = &bh[nt >> 1][(nt & 1) << 1];
                    const uint32_t* Blf = &bl[nt >> 1][(nt & 1) << 1];
                    mma16816(acc[mt][nt], ah[mt], Bhf);
                    mma16816(acc[mt][nt], ah[mt], Blf);
                    mma16816(acc[mt][nt], al[mt], Bhf);
                }
        }
    }

    // ---------------- epilogue ----------------
    const int lr = lid >> 2, lc = (lid & 3) << 1;
#pragma unroll
    for (int mt = 0; mt < 4; mt++) {
        int row0 = bm + wm * 64 + mt * 16 + lr;
        float ga0 = gate[row0], ga1 = gate[row0 + 8];
        float gb0 = (EPI == 1) ? gate[NT + row0] : 0.f;
        float gb1 = (EPI == 1) ? gate[NT + row0 + 8] : 0.f;
#pragma unroll
        for (int nt = 0; nt < 8; nt++) {
            int col = bn + wn * 64 + nt * 8 + lc;
            float b00 = bias0[col], b01 = bias0[col + 1];
            float b10 = (EPI == 1) ? bias1[col] : 0.f;
            float b11 = (EPI == 1) ? bias1[col + 1] : 0.f;
#pragma unroll
            for (int h = 0; h < 2; h++) {
                int row = row0 + h * 8;
                size_t o = (size_t)row * ldc + coff + col;
                if (EPI == 0) {
                    float g = h ? ga1 : ga0;
                    float v0 = acc[mt][nt][2 * h + 0] + b00;
                    float v1 = acc[mt][nt][2 * h + 1] + b01;
                    v0 = g * (0.5f * v0 * (1.0f + erff(v0 * 0.70710678118654752f)));
                    v1 = g * (0.5f * v1 * (1.0f + erff(v1 * 0.70710678118654752f)));
                    __nv_bfloat16 h0 = __float2bfloat16(v0);
                    __nv_bfloat16 h1 = __float2bfloat16(v1);
                    __nv_bfloat162 hh; hh.x = h0; hh.y = h1;
                    __nv_bfloat162 ll;
                    ll.x = __float2bfloat16(v0 - __bfloat162float(h0));
                    ll.y = __float2bfloat16(v1 - __bfloat162float(h1));
                    *reinterpret_cast<__nv_bfloat162*>(Ch + o) = hh;
                    *reinterpret_cast<__nv_bfloat162*>(Cl + o) = ll;
                } else {
                    float g0 = h ? ga1 : ga0, g1 = h ? gb1 : gb0;
                    float2 w;
                    w.x = acc[mt][nt][2 * h + 0] + g0 * b00 + g1 * b10;
                    w.y = acc[mt][nt][2 * h + 1] + g0 * b01 + g1 * b11;
                    *reinterpret_cast<float2*>(Cf + o) = w;
                }
            }
        }
    }
}

// ---------------- launch ----------------
extern "C" void kernel_launch(void* const* d_in, const int* in_sizes, int n_in,
                              void* d_out, int out_size) {
    const float* x   = (const float*)d_in[0];
    const int*   ids = (const int*)d_in[1];
    const float* tw  = (const float*)d_in[2];
    const float* W1[2] = {(const float*)d_in[3], (const float*)d_in[7]};
    const float* b1[2] = {(const float*)d_in[4], (const float*)d_in[8]};
    const float* W2[2] = {(const float*)d_in[5], (const float*)d_in[9]};
    const float* b2[2] = {(const float*)d_in[6], (const float*)d_in[10]};
    float* out = (float*)d_out;

    __nv_bfloat16 *Xh, *Xl, *Hh, *Hl, *W1t, *W2t;
    float* gate;
    cudaGetSymbolAddress((void**)&Xh, g_Xh);
    cudaGetSymbolAddress((void**)&Xl, g_Xl);
    cudaGetSymbolAddress((void**)&Hh, g_Hh);
    cudaGetSymbolAddress((void**)&Hl, g_Hl);
    cudaGetSymbolAddress((void**)&W1t, g_W1t);
    cudaGetSymbolAddress((void**)&W2t, g_W2t);
    cudaGetSymbolAddress((void**)&gate, g_gate);

    cudaFuncSetAttribute(moe_gemm<0>, cudaFuncAttributeMaxDynamicSharedMemorySize, SMEM_BYTES);
    cudaFuncSetAttribute(moe_gemm<1>, cudaFuncAttributeMaxDynamicSharedMemorySize, SMEM_BYTES);

    gate_k<<<(NT + 255) / 256, 256>>>(ids, tw, gate);
    {
        size_t n = (size_t)NT * DM;
        split_k<<<(unsigned)((n + 255) / 256), 256>>>(x, Xh, Xl, n);
    }
    for (int e = 0; e < 2; e++) {
        transpose_split<<<dim3(DF / 32, DM / 32), dim3(32, 8)>>>(
            W1[e], W1t + ((size_t)e * 2 + 0) * DF * DM, W1t + ((size_t)e * 2 + 1) * DF * DM,
            DM, DF);
        transpose_split<<<dim3(DM / 32, DF / 32), dim3(32, 8)>>>(
            W2[e], W2t + ((size_t)e * 2 + 0) * DM * DF, W2t + ((size_t)e * 2 + 1) * DM * DF,
            DF, DM);
    }

    dim3 blk(256);
    dim3 g1(DF / BN, NT / BM);   // (32, 64) per expert
    dim3 g2(DM / BN, NT / BM);   // (8, 64)
    const int BIG = 1 << 30;

    // GEMM1 per expert: H[:, e*DF : (e+1)*DF] = gate_e * GELU(X @ W1_e + b1_e), split hi/lo
    for (int e = 0; e < 2; e++) {
        const __nv_bfloat16* wh = W1t + ((size_t)e * 2 + 0) * DF * DM;
        const __nv_bfloat16* wl = W1t + ((size_t)e * 2 + 1) * DF * DM;
        moe_gemm<0><<<g1, blk, SMEM_BYTES>>>(
            Xh, Xl, wh, wl, wh, wl, b1[e], nullptr, gate + (size_t)e * NT,
            nullptr, Hh, Hl, DM, DM, DM, 2 * DF, BIG, e * DF);
    }
    // GEMM2 combined: out = Hs @ [W2_0; W2_1] + g0*b2_0 + g1*b2_1, K = 16384
    moe_gemm<1><<<g2, blk, SMEM_BYTES>>>(
        Hh, Hl,
        W2t + 0 * (size_t)DM * DF, W2t + 1 * (size_t)DM * DF,
        W2t + 2 * (size_t)DM * DF, W2t + 3 * (size_t)DM * DF,
        b2[0], b2[1], gate, out, nullptr, nullptr,
        2 * DF, 2 * DF, DF, DM, DF / BK, 0);
}

// round 6
// speedup vs baseline: 3.1966x; 1.0149x over previous
#include <cuda_runtime.h>
#include <cuda_bf16.h>
#include <cstdint>
#include <math.h>

#define DM 2048
#define DF 8192
#define NT 8192

// ---------------- scratch ----------------
__device__ __align__(256) __nv_bfloat16 g_Xh[(size_t)NT * DM];
__device__ __align__(256) __nv_bfloat16 g_Xl[(size_t)NT * DM];
__device__ __align__(256) __nv_bfloat16 g_Hh[(size_t)NT * 2 * DF];
__device__ __align__(256) __nv_bfloat16 g_Hl[(size_t)NT * 2 * DF];
__device__ __align__(256) __nv_bfloat16 g_W1t[2][2][(size_t)DF * DM];
__device__ __align__(256) __nv_bfloat16 g_W2t[2][2][(size_t)DM * DF];
__device__ float g_gate[2 * NT];

// ---------------- helpers ----------------
__device__ __forceinline__ uint32_t smem_u32(const void* p) {
    uint32_t a;
    asm("{ .reg .u64 t; cvta.to.shared.u64 t, %1; cvt.u32.u64 %0, t; }" : "=r"(a) : "l"(p));
    return a;
}
#define CP_ASYNC16(sa, g) \
    asm volatile("cp.async.cg.shared.global [%0], [%1], 16;" :: "r"(sa), "l"(g))
#define CP_COMMIT() asm volatile("cp.async.commit_group;" ::: "memory")
#define CP_WAIT(n)  asm volatile("cp.async.wait_group %0;" :: "n"(n) : "memory")

#define LDSM_X4(r0, r1, r2, r3, a) \
    asm volatile("ldmatrix.sync.aligned.m8n8.x4.shared.b16 {%0,%1,%2,%3}, [%4];" \
                 : "=r"(r0), "=r"(r1), "=r"(r2), "=r"(r3) : "r"(a))

__device__ __forceinline__ void mma16816(float* d, const uint32_t* a, const uint32_t* b) {
    asm volatile(
        "mma.sync.aligned.m16n8k16.row.col.f32.bf16.bf16.f32 "
        "{%0,%1,%2,%3}, {%4,%5,%6,%7}, {%8,%9}, {%0,%1,%2,%3};"
        : "+f"(d[0]), "+f"(d[1]), "+f"(d[2]), "+f"(d[3])
        : "r"(a[0]), "r"(a[1]), "r"(a[2]), "r"(a[3]), "r"(b[0]), "r"(b[1]));
}

__device__ __forceinline__ uint32_t swz(uint32_t r, uint32_t s) {
    return ((r >> 1) << 7) + (((((r & 1) << 2) | s) ^ ((r >> 1) & 7)) << 4);
}
__device__ __forceinline__ uint32_t pack_bf2(float a, float b) {
    __nv_bfloat162 v;
    v.x = __float2bfloat16(a);
    v.y = __float2bfloat16(b);
    return *reinterpret_cast<uint32_t*>(&v);
}

// ---------------- prep kernels ----------------
__global__ void gate_k(const int* __restrict__ ids, const float* __restrict__ w,
                       float* __restrict__ gate) {
    int i = blockIdx.x * blockDim.x + threadIdx.x;
    if (i >= NT) return;
    int a = ids[2 * i] & 1, b = ids[2 * i + 1] & 1;
    float wa = w[2 * i], wb = w[2 * i + 1];
    gate[i]      = (a ? 0.f : wa) + (b ? 0.f : wb);
    gate[NT + i] = (a ? wa : 0.f) + (b ? wb : 0.f);
}

// vectorized split: 4 floats -> 2x bf16x2 hi + 2x bf16x2 lo
__global__ void split_k(const float4* __restrict__ x4, uint2* __restrict__ hi,
                        uint2* __restrict__ lo, size_t n4) {
    size_t i = (size_t)blockIdx.x * blockDim.x + threadIdx.x;
    if (i >= n4) return;
    float4 v = x4[i];
    float h0 = __bfloat162float(__float2bfloat16(v.x));
    float h1 = __bfloat162float(__float2bfloat16(v.y));
    float h2 = __bfloat162float(__float2bfloat16(v.z));
    float h3 = __bfloat162float(__float2bfloat16(v.w));
    uint2 H, L;
    H.x = pack_bf2(h0, h1);         H.y = pack_bf2(h2, h3);
    L.x = pack_bf2(v.x - h0, v.y - h1);
    L.y = pack_bf2(v.z - h2, v.w - h3);
    hi[i] = H;
    lo[i] = L;
}

// W [K][N] f32 -> Wt hi/lo [N][K] bf16 (64k x 32n tiles, bf16x2 stores)
__global__ void transpose_split(const float* __restrict__ W,
                                __nv_bfloat16* __restrict__ th,
                                __nv_bfloat16* __restrict__ tl, int K, int N) {
    __shared__ float tile[64][33];
    int k0 = blockIdx.y * 64, n0 = blockIdx.x * 32;
    int tx = threadIdx.x, ty = threadIdx.y;
    for (int r = ty; r < 64; r += 8)
        tile[r][tx] = W[(size_t)(k0 + r) * N + n0 + tx];
    __syncthreads();
    for (int rn = ty; rn < 32; rn += 8) {
        float v0 = tile[2 * tx][rn], v1 = tile[2 * tx + 1][rn];
        float h0 = __bfloat162float(__float2bfloat16(v0));
        float h1 = __bfloat162float(__float2bfloat16(v1));
        size_t o = ((size_t)(n0 + rn) * K + k0 + 2 * tx) >> 1;
        reinterpret_cast<uint32_t*>(th)[o] = pack_bf2(h0, h1);
        reinterpret_cast<uint32_t*>(tl)[o] = pack_bf2(v0 - h0, v1 - h1);
    }
}

// ---------------- mma.sync split-bf16 GEMM, 128x256 CTA, 512 threads ----------------
static constexpr int BM = 128, BN = 256, BK = 32;
static constexpr int STAGES = 4;
static constexpr int A_TILE_B = BM * 64;
static constexpr int B_TILE_B = BN * 64;
static constexpr int STAGE_B = 2 * A_TILE_B + 2 * B_TILE_B;  // 49152
static constexpr int SMEM_BYTES = STAGES * STAGE_B;           // 196608
static constexpr int O_AH = 0, O_AL = A_TILE_B;
static constexpr int O_BH = 2 * A_TILE_B, O_BL = 2 * A_TILE_B + B_TILE_B;
static constexpr int NTHR = 512;

template <int ITERS>
__device__ __forceinline__ void load_pair(uint32_t sdst_h, uint32_t sdst_l,
                                          const __nv_bfloat16* __restrict__ gh,
                                          const __nv_bfloat16* __restrict__ gl,
                                          int ld, int t) {
#pragma unroll
    for (int i = 0; i < ITERS; i++) {
        uint32_t idx = t + i * NTHR;
        uint32_t r = idx >> 2, s = idx & 3;
        uint32_t off = swz(r, s);
        size_t go = (size_t)r * ld + s * 8;
        CP_ASYNC16(sdst_h + off, gh + go);
        CP_ASYNC16(sdst_l + off, gl + go);
    }
}

// EPI 0: Ch/Cl = split(gate[row]*GELU(v+bias0));  EPI 1: Cf = v + g0*b0 + g1*b1
template <int EPI>
__global__ void __launch_bounds__(NTHR, 1)
moe_gemm(const __nv_bfloat16* __restrict__ Ah, const __nv_bfloat16* __restrict__ Al,
         const __nv_bfloat16* __restrict__ Bh0, const __nv_bfloat16* __restrict__ Bl0,
         const __nv_bfloat16* __restrict__ Bh1, const __nv_bfloat16* __restrict__ Bl1,
         const float* __restrict__ bias0, const float* __restrict__ bias1,
         const float* __restrict__ gate,
         float* __restrict__ Cf, __nv_bfloat16* __restrict__ Ch,
         __nv_bfloat16* __restrict__ Cl,
         int K, int lda, int ldb, int ldc, int k_split, int coff) {
    extern __shared__ char smem[];
    const uint32_t sb = smem_u32(smem);
    const int t = threadIdx.x, wid = t >> 5, lid = t & 31;
    const int wm = wid >> 2, wn = wid & 3;   // 4x4 warp grid; warp tile 32x64
    const int bm = blockIdx.y * BM, bn = blockIdx.x * BN;
    const int NC = K / BK;

    const __nv_bfloat16* a_h = Ah + (size_t)bm * lda;
    const __nv_bfloat16* a_l = Al + (size_t)bm * lda;

    float acc[2][8][4];
#pragma unroll
    for (int i = 0; i < 2; i++)
#pragma unroll
        for (int j = 0; j < 8; j++)
#pragma unroll
            for (int q = 0; q < 4; q++) acc[i][j][q] = 0.f;

#pragma unroll
    for (int p = 0; p < STAGES - 1; p++) {
        uint32_t st = sb + p * STAGE_B;
        int e = (p >= k_split);
        int kb = (p - (e ? k_split : 0)) * BK;
        const __nv_bfloat16* bh = (e ? Bh1 : Bh0) + (size_t)bn * ldb + kb;
        const __nv_bfloat16* bl = (e ? Bl1 : Bl0) + (size_t)bn * ldb + kb;
        load_pair<1>(st + O_AH, st + O_AL, a_h + p * BK, a_l + p * BK, lda, t);
        load_pair<2>(st + O_BH, st + O_BL, bh, bl, ldb, t);
        CP_COMMIT();
    }

    const uint32_t a_r = (uint32_t)(lid & 15);
    const uint32_t a_s = (uint32_t)(lid >> 4);
    const uint32_t b_r = (uint32_t)((lid & 7) + ((lid >> 4) << 3));
    const uint32_t b_s = (uint32_t)((lid >> 3) & 1);

    for (int c = 0; c < NC; c++) {
        CP_WAIT(STAGES - 2);
        __syncthreads();
        if (c + STAGES - 1 < NC) {
            int cc = c + STAGES - 1;
            uint32_t st = sb + (cc % STAGES) * STAGE_B;
            int e = (cc >= k_split);
            int kb = (cc - (e ? k_split : 0)) * BK;
            const __nv_bfloat16* bh = (e ? Bh1 : Bh0) + (size_t)bn * ldb + kb;
            const __nv_bfloat16* bl = (e ? Bl1 : Bl0) + (size_t)bn * ldb + kb;
            load_pair<1>(st + O_AH, st + O_AL, a_h + cc * BK, a_l + cc * BK, lda, t);
            load_pair<2>(st + O_BH, st + O_BL, bh, bl, ldb, t);
        }
        CP_COMMIT();

        const uint32_t st = sb + (c % STAGES) * STAGE_B;
#pragma unroll
        for (int kk = 0; kk < 2; kk++) {
            uint32_t ah[2][4], al[2][4];
#pragma unroll
            for (int mt = 0; mt < 2; mt++) {
                uint32_t off = swz(wm * 32 + mt * 16 + a_r, kk * 2 + a_s);
                LDSM_X4(ah[mt][0], ah[mt][1], ah[mt][2], ah[mt][3], st + O_AH + off);
                LDSM_X4(al[mt][0], al[mt][1], al[mt][2], al[mt][3], st + O_AL + off);
            }
#pragma unroll
            for (int h2 = 0; h2 < 2; h2++) {   // two n32 halves -> small B live range
                uint32_t bh[2][4], bl[2][4];
#pragma unroll
                for (int pp = 0; pp < 2; pp++) {
                    int p = h2 * 2 + pp;
                    uint32_t off = swz(wn * 64 + p * 16 + b_r, kk * 2 + b_s);
                    LDSM_X4(bh[pp][0], bh[pp][1], bh[pp][2], bh[pp][3], st + O_BH + off);
                    LDSM_X4(bl[pp][0], bl[pp][1], bl[pp][2], bl[pp][3], st + O_BL + off);
                }
#pragma unroll
                for (int mt = 0; mt < 2; mt++)
#pragma unroll
                    for (int ntl = 0; ntl < 4; ntl++) {
                        int nt = h2 * 4 + ntl;
                        const uint32_t* Bhf = &bh[ntl >> 1][(ntl & 1) << 1];
                        const uint32_t* Blf = &bl[ntl >> 1][(ntl & 1) << 1];
                        mma16816(acc[mt][nt], ah[mt], Bhf);
                        mma16816(acc[mt][nt], ah[mt], Blf);
                        mma16816(acc[mt][nt], al[mt], Bhf);
                    }
            }
        }
    }

    // ---------------- epilogue ----------------
    const int lr = lid >> 2, lc = (lid & 3) << 1;
#pragma unroll
    for (int mt = 0; mt < 2; mt++) {
        int row0 = bm + wm * 32 + mt * 16 + lr;
        float ga0 = gate[row0], ga1 = gate[row0 + 8];
        float gb0 = (EPI == 1) ? gate[NT + row0] : 0.f;
        float gb1 = (EPI == 1) ? gate[NT + row0 + 8] : 0.f;
#pragma unroll
        for (int nt = 0; nt < 8; nt++) {
            int col = bn + wn * 64 + nt * 8 + lc;
            float b00 = bias0[col], b01 = bias0[col + 1];
            float b10 = (EPI == 1) ? bias1[col] : 0.f;
            float b11 = (EPI == 1) ? bias1[col + 1] : 0.f;
#pragma unroll
            for (int h = 0; h < 2; h++) {
                int row = row0 + h * 8;
                size_t o = (size_t)row * ldc + coff + col;
                if (EPI == 0) {
                    float g = h ? ga1 : ga0;
                    float v0 = acc[mt][nt][2 * h + 0] + b00;
                    float v1 = acc[mt][nt][2 * h + 1] + b01;
                    v0 = g * (0.5f * v0 * (1.0f + erff(v0 * 0.70710678118654752f)));
                    v1 = g * (0.5f * v1 * (1.0f + erff(v1 * 0.70710678118654752f)));
                    float h0 = __bfloat162float(__float2bfloat16(v0));
                    float h1 = __bfloat162float(__float2bfloat16(v1));
                    *reinterpret_cast<uint32_t*>(Ch + o) = pack_bf2(h0, h1);
                    *reinterpret_cast<uint32_t*>(Cl + o) = pack_bf2(v0 - h0, v1 - h1);
                } else {
                    float g0 = h ? ga1 : ga0, g1 = h ? gb1 : gb0;
                    float2 w;
                    w.x = acc[mt][nt][2 * h + 0] + g0 * b00 + g1 * b10;
                    w.y = acc[mt][nt][2 * h + 1] + g0 * b01 + g1 * b11;
                    *reinterpret_cast<float2*>(Cf + o) = w;
                }
            }
        }
    }
}

// ---------------- launch ----------------
extern "C" void kernel_launch(void* const* d_in, const int* in_sizes, int n_in,
                              void* d_out, int out_size) {
    const float* x   = (const float*)d_in[0];
    const int*   ids = (const int*)d_in[1];
    const float* tw  = (const float*)d_in[2];
    const float* W1[2] = {(const float*)d_in[3], (const float*)d_in[7]};
    const float* b1[2] = {(const float*)d_in[4], (const float*)d_in[8]};
    const float* W2[2] = {(const float*)d_in[5], (const float*)d_in[9]};
    const float* b2[2] = {(const float*)d_in[6], (const float*)d_in[10]};
    float* out = (float*)d_out;

    __nv_bfloat16 *Xh, *Xl, *Hh, *Hl, *W1t, *W2t;
    float* gate;
    cudaGetSymbolAddress((void**)&Xh, g_Xh);
    cudaGetSymbolAddress((void**)&Xl, g_Xl);
    cudaGetSymbolAddress((void**)&Hh, g_Hh);
    cudaGetSymbolAddress((void**)&Hl, g_Hl);
    cudaGetSymbolAddress((void**)&W1t, g_W1t);
    cudaGetSymbolAddress((void**)&W2t, g_W2t);
    cudaGetSymbolAddress((void**)&gate, g_gate);

    cudaFuncSetAttribute(moe_gemm<0>, cudaFuncAttributeMaxDynamicSharedMemorySize, SMEM_BYTES);
    cudaFuncSetAttribute(moe_gemm<1>, cudaFuncAttributeMaxDynamicSharedMemorySize, SMEM_BYTES);

    gate_k<<<(NT + 255) / 256, 256>>>(ids, tw, gate);
    {
        size_t n4 = (size_t)NT * DM / 4;
        split_k<<<(unsigned)((n4 + 255) / 256), 256>>>(
            (const float4*)x, (uint2*)Xh, (uint2*)Xl, n4);
    }
    for (int e = 0; e < 2; e++) {
        transpose_split<<<dim3(DF / 32, DM / 64), dim3(32, 8)>>>(
            W1[e], W1t + ((size_t)e * 2 + 0) * DF * DM, W1t + ((size_t)e * 2 + 1) * DF * DM,
            DM, DF);
        transpose_split<<<dim3(DM / 32, DF / 64), dim3(32, 8)>>>(
            W2[e], W2t + ((size_t)e * 2 + 0) * DM * DF, W2t + ((size_t)e * 2 + 1) * DM * DF,
            DF, DM);
    }

    dim3 blk(NTHR);
    dim3 g1(DF / BN, NT / BM);   // (32, 64) per expert
    dim3 g2(DM / BN, NT / BM);   // (8, 64)
    const int BIG = 1 << 30;

    for (int e = 0; e < 2; e++) {
        const __nv_bfloat16* wh = W1t + ((size_t)e * 2 + 0) * DF * DM;
        const __nv_bfloat16* wl = W1t + ((size_t)e * 2 + 1) * DF * DM;
        moe_gemm<0><<<g1, blk, SMEM_BYTES>>>(
            Xh, Xl, wh, wl, wh, wl, b1[e], nullptr, gate + (size_t)e * NT,
            nullptr, Hh, Hl, DM, DM, DM, 2 * DF, BIG, e * DF);
    }
    moe_gemm<1><<<g2, blk, SMEM_BYTES>>>(
        Hh, Hl,
        W2t + 0 * (size_t)DM * DF, W2t + 1 * (size_t)DM * DF,
        W2t + 2 * (size_t)DM * DF, W2t + 3 * (size_t)DM * DF,
        b2[0], b2[1], gate, out, nullptr, nullptr,
        2 * DF, 2 * DF, DF, DM, DF / BK, 0);
}

// round 8
// speedup vs baseline: 8.5802x; 2.6842x over previous
#include <cuda_runtime.h>
#include <cuda_fp16.h>
#include <cstdint>
#include <math.h>

#define DM 2048
#define DF 8192
#define NT 8192

// ---------------- scratch ----------------
__device__ __align__(256) __half g_X[(size_t)NT * DM];
__device__ __align__(256) __half g_H[(size_t)NT * 2 * DF];     // [NT][2*DF], gate pre-scaled
__device__ __align__(256) __half g_W1t[2][(size_t)DF * DM];    // [expert][N][K]
__device__ __align__(256) __half g_W2t[2][(size_t)DM * DF];
__device__ float g_gate[2 * NT];

// ---------------- helpers ----------------
__device__ __forceinline__ uint32_t smem_u32(const void* p) {
    uint32_t a;
    asm("{ .reg .u64 t; cvta.to.shared.u64 t, %1; cvt.u32.u64 %0, t; }" : "=r"(a) : "l"(p));
    return a;
}
#define CP_ASYNC16(sa, g) \
    asm volatile("cp.async.cg.shared.global [%0], [%1], 16;" :: "r"(sa), "l"(g))
#define CP_COMMIT() asm volatile("cp.async.commit_group;" ::: "memory")
#define CP_WAIT(n)  asm volatile("cp.async.wait_group %0;" :: "n"(n) : "memory")

#define LDSM_X4(r0, r1, r2, r3, a) \
    asm volatile("ldmatrix.sync.aligned.m8n8.x4.shared.b16 {%0,%1,%2,%3}, [%4];" \
                 : "=r"(r0), "=r"(r1), "=r"(r2), "=r"(r3) : "r"(a))

__device__ __forceinline__ void mma16816(float* d, const uint32_t* a, const uint32_t* b) {
    asm volatile(
        "mma.sync.aligned.m16n8k16.row.col.f32.f16.f16.f32 "
        "{%0,%1,%2,%3}, {%4,%5,%6,%7}, {%8,%9}, {%0,%1,%2,%3};"
        : "+f"(d[0]), "+f"(d[1]), "+f"(d[2]), "+f"(d[3])
        : "r"(a[0]), "r"(a[1]), "r"(a[2]), "r"(a[3]), "r"(b[0]), "r"(b[1]));
}

// 128B rows, 8x 16B segments, XOR swizzle
__device__ __forceinline__ uint32_t swz(uint32_t r, uint32_t s) {
    return (r << 7) + ((s ^ (r & 7)) << 4);
}
__device__ __forceinline__ uint32_t pack_h2(float a, float b) {
    __half2 v = __floats2half2_rn(a, b);
    return *reinterpret_cast<uint32_t*>(&v);
}

// ---------------- prep kernels ----------------
__global__ void gate_k(const int* __restrict__ ids, const float* __restrict__ w,
                       float* __restrict__ gate) {
    int i = blockIdx.x * blockDim.x + threadIdx.x;
    if (i >= NT) return;
    int a = ids[2 * i] & 1, b = ids[2 * i + 1] & 1;
    float wa = w[2 * i], wb = w[2 * i + 1];
    gate[i]      = (a ? 0.f : wa) + (b ? 0.f : wb);
    gate[NT + i] = (a ? wa : 0.f) + (b ? wb : 0.f);
}

__global__ void conv_k(const float4* __restrict__ x4, uint2* __restrict__ o, size_t n4) {
    size_t i = (size_t)blockIdx.x * blockDim.x + threadIdx.x;
    if (i >= n4) return;
    float4 v = x4[i];
    uint2 r;
    r.x = pack_h2(v.x, v.y);
    r.y = pack_h2(v.z, v.w);
    o[i] = r;
}

// W [K][N] f32 -> T [N][K] fp16; both experts via blockIdx.z
__global__ void transpose_h(const float* __restrict__ W0, const float* __restrict__ W1,
                            __half* __restrict__ T0, __half* __restrict__ T1,
                            int K, int N) {
    __shared__ float tile[64][33];
    const float* W = blockIdx.z ? W1 : W0;
    __half* T = blockIdx.z ? T1 : T0;
    int k0 = blockIdx.y * 64, n0 = blockIdx.x * 32;
    int tx = threadIdx.x, ty = threadIdx.y;
    for (int r = ty; r < 64; r += 8)
        tile[r][tx] = W[(size_t)(k0 + r) * N + n0 + tx];
    __syncthreads();
    for (int rn = ty; rn < 32; rn += 8) {
        float v0 = tile[2 * tx][rn], v1 = tile[2 * tx + 1][rn];
        size_t o = ((size_t)(n0 + rn) * K + k0 + 2 * tx) >> 1;
        reinterpret_cast<uint32_t*>(T)[o] = pack_h2(v0, v1);
    }
}

// ---------------- fp16 mma.sync GEMM: CTA 128x256, BK=64, 512 threads ----------------
static constexpr int BM = 128, BN = 256, BK = 64;
static constexpr int STAGES = 4;
static constexpr int A_TILE_B = BM * 128;                      // 16384
static constexpr int B_TILE_B = BN * 128;                      // 32768
static constexpr int STAGE_B = A_TILE_B + B_TILE_B;            // 49152
static constexpr int SMEM_BYTES = STAGES * STAGE_B;            // 196608
static constexpr int O_A = 0, O_B = A_TILE_B;
static constexpr int NTHR = 512;

template <int ITERS>
__device__ __forceinline__ void load_tile(uint32_t sdst, const __half* __restrict__ g,
                                          int ld, int t) {
#pragma unroll
    for (int i = 0; i < ITERS; i++) {
        uint32_t idx = t + i * NTHR;
        uint32_t r = idx >> 3, s = idx & 7;
        CP_ASYNC16(sdst + swz(r, s), g + (size_t)r * ld + s * 8);
    }
}

// EPI 0: Ch = fp16(gate[row]*GELU(v+bias0))   EPI 1: Cf = v + g0*b0 + g1*b1
template <int EPI>
__global__ void __launch_bounds__(NTHR, 1)
moe_gemm(const __half* __restrict__ A,
         const __half* __restrict__ B0, const __half* __restrict__ B1,
         const float* __restrict__ bias0, const float* __restrict__ bias1,
         const float* __restrict__ gate,
         float* __restrict__ Cf, __half* __restrict__ Ch,
         int K, int lda, int ldb, int ldc, int k_split, int coff) {
    extern __shared__ char smem[];
    const uint32_t sb = smem_u32(smem);
    const int t = threadIdx.x, wid = t >> 5, lid = t & 31;
    const int wm = wid >> 2, wn = wid & 3;   // 4x4 warp grid; warp tile 32x64
    const int bm = blockIdx.y * BM, bn = blockIdx.x * BN;
    const int NC = K / BK;

    const __half* a_g = A + (size_t)bm * lda;

    float acc[2][8][4];
#pragma unroll
    for (int i = 0; i < 2; i++)
#pragma unroll
        for (int j = 0; j < 8; j++)
#pragma unroll
            for (int q = 0; q < 4; q++) acc[i][j][q] = 0.f;

#pragma unroll
    for (int p = 0; p < STAGES - 1; p++) {
        uint32_t st = sb + p * STAGE_B;
        int e = (p >= k_split);
        int kb = (p - (e ? k_split : 0)) * BK;
        load_tile<2>(st + O_A, a_g + p * BK, lda, t);                          // 128 rows x 8 segs
        load_tile<4>(st + O_B, (e ? B1 : B0) + (size_t)bn * ldb + kb, ldb, t); // 256 rows x 8 segs
        CP_COMMIT();
    }

    const uint32_t a_r = (uint32_t)(lid & 15);
    const uint32_t a_s = (uint32_t)(lid >> 4);
    const uint32_t b_r = (uint32_t)((lid & 7) + ((lid >> 4) << 3));
    const uint32_t b_s = (uint32_t)((lid >> 3) & 1);

    for (int c = 0; c < NC; c++) {
        CP_WAIT(STAGES - 2);
        __syncthreads();
        if (c + STAGES - 1 < NC) {
            int cc = c + STAGES - 1;
            uint32_t st = sb + (cc % STAGES) * STAGE_B;
            int e = (cc >= k_split);
            int kb = (cc - (e ? k_split : 0)) * BK;
            load_tile<2>(st + O_A, a_g + cc * BK, lda, t);
            load_tile<4>(st + O_B, (e ? B1 : B0) + (size_t)bn * ldb + kb, ldb, t);
        }
        CP_COMMIT();

        const uint32_t st = sb + (c % STAGES) * STAGE_B;
#pragma unroll
        for (int kk = 0; kk < 4; kk++) {   // 4 k16 steps in BK=64
            uint32_t ah[2][4], bh[4][4];
#pragma unroll
            for (int mt = 0; mt < 2; mt++) {
                uint32_t off = swz(wm * 32 + mt * 16 + a_r, kk * 2 + a_s);
                LDSM_X4(ah[mt][0], ah[mt][1], ah[mt][2], ah[mt][3], st + O_A + off);
            }
#pragma unroll
            for (int p = 0; p < 4; p++) {  // 4 n16 groups = 64 cols
                uint32_t off = swz(wn * 64 + p * 16 + b_r, kk * 2 + b_s);
                LDSM_X4(bh[p][0], bh[p][1], bh[p][2], bh[p][3], st + O_B + off);
            }
#pragma unroll
            for (int mt = 0; mt < 2; mt++)
#pragma unroll
                for (int nt = 0; nt < 8; nt++)
                    mma16816(acc[mt][nt], ah[mt], &bh[nt >> 1][(nt & 1) << 1]);
        }
    }

    // ---------------- epilogue ----------------
    const int lr = lid >> 2, lc = (lid & 3) << 1;
#pragma unroll
    for (int mt = 0; mt < 2; mt++) {
        int row0 = bm + wm * 32 + mt * 16 + lr;
        float ga0 = gate[row0], ga1 = gate[row0 + 8];
        float gb0 = (EPI == 1) ? gate[NT + row0] : 0.f;
        float gb1 = (EPI == 1) ? gate[NT + row0 + 8] : 0.f;
#pragma unroll
        for (int nt = 0; nt < 8; nt++) {
            int col = bn + wn * 64 + nt * 8 + lc;
            float b00 = bias0[col], b01 = bias0[col + 1];
            float b10 = (EPI == 1) ? bias1[col] : 0.f;
            float b11 = (EPI == 1) ? bias1[col + 1] : 0.f;
#pragma unroll
            for (int h = 0; h < 2; h++) {
                int row = row0 + h * 8;
                size_t o = (size_t)row * ldc + coff + col;
                if (EPI == 0) {
                    float g = h ? ga1 : ga0;
                    float v0 = acc[mt][nt][2 * h + 0] + b00;
                    float v1 = acc[mt][nt][2 * h + 1] + b01;
                    v0 = g * (0.5f * v0 * (1.0f + erff(v0 * 0.70710678118654752f)));
                    v1 = g * (0.5f * v1 * (1.0f + erff(v1 * 0.70710678118654752f)));
                    *reinterpret_cast<uint32_t*>(Ch + o) = pack_h2(v0, v1);
                } else {
                    float g0 = h ? ga1 : ga0, g1 = h ? gb1 : gb0;
                    float2 w;
                    w.x = acc[mt][nt][2 * h + 0] + g0 * b00 + g1 * b10;
                    w.y = acc[mt][nt][2 * h + 1] + g0 * b01 + g1 * b11;
                    *reinterpret_cast<float2*>(Cf + o) = w;
                }
            }
        }
    }
}

// ---------------- launch ----------------
extern "C" void kernel_launch(void* const* d_in, const int* in_sizes, int n_in,
                              void* d_out, int out_size) {
    const float* x   = (const float*)d_in[0];
    const int*   ids = (const int*)d_in[1];
    const float* tw  = (const float*)d_in[2];
    const float* W1[2] = {(const float*)d_in[3], (const float*)d_in[7]};
    const float* b1[2] = {(const float*)d_in[4], (const float*)d_in[8]};
    const float* W2[2] = {(const float*)d_in[5], (const float*)d_in[9]};
    const float* b2[2] = {(const float*)d_in[6], (const float*)d_in[10]};
    float* out = (float*)d_out;

    __half *X, *H, *W1t, *W2t;
    float* gate;
    cudaGetSymbolAddress((void**)&X, g_X);
    cudaGetSymbolAddress((void**)&H, g_H);
    cudaGetSymbolAddress((void**)&W1t, g_W1t);
    cudaGetSymbolAddress((void**)&W2t, g_W2t);
    cudaGetSymbolAddress((void**)&gate, g_gate);

    cudaFuncSetAttribute(moe_gemm<0>, cudaFuncAttributeMaxDynamicSharedMemorySize, SMEM_BYTES);
    cudaFuncSetAttribute(moe_gemm<1>, cudaFuncAttributeMaxDynamicSharedMemorySize, SMEM_BYTES);

    // launches 1-4 (prep), 5-6 (GEMM1; #6 is what ncu -s 5 -c 1 captures), 7 (GEMM2)
    gate_k<<<(NT + 255) / 256, 256>>>(ids, tw, gate);
    {
        size_t n4 = (size_t)NT * DM / 4;
        conv_k<<<(unsigned)((n4 + 255) / 256), 256>>>((const float4*)x, (uint2*)X, n4);
    }
    transpose_h<<<dim3(DF / 32, DM / 64, 2), dim3(32, 8)>>>(
        W1[0], W1[1], W1t, W1t + (size_t)DF * DM, DM, DF);
    transpose_h<<<dim3(DM / 32, DF / 64, 2), dim3(32, 8)>>>(
        W2[0], W2[1], W2t, W2t + (size_t)DM * DF, DF, DM);

    dim3 blk(NTHR);
    dim3 g1(DF / BN, NT / BM);   // (32, 64) per expert
    dim3 g2(DM / BN, NT / BM);   // (8, 64)
    const int BIG = 1 << 30;

    for (int e = 0; e < 2; e++) {
        moe_gemm<0><<<g1, blk, SMEM_BYTES>>>(
            X, W1t + (size_t)e * DF * DM, W1t + (size_t)e * DF * DM,
            b1[e], nullptr, gate + (size_t)e * NT,
            nullptr, H, DM, DM, DM, 2 * DF, BIG, e * DF);
    }
    moe_gemm<1><<<g2, blk, SMEM_BYTES>>>(
        H, W2t, W2t + (size_t)DM * DF,
        b2[0], b2[1], gate, out, nullptr,
        2 * DF, 2 * DF, DF, DM, DF / BK, 0);
}